// round 7
// baseline (speedup 1.0000x reference)
#include <cuda_runtime.h>
#include <math.h>

#define S 2048
#define E 512
#define HD 512
#define G4 2048   /* 4*HD */
#define NT 12     /* tags */
#define NDIRCTA 64

// ---------------- scratch (device globals; no runtime allocation) ----------
__device__ float g_xp[2][S][G4];     // input projections + bias, both dirs (32 MB)
__device__ float g_hs[2][S][HD];     // hidden states, both dirs (8 MB)
__device__ float g_feats[S][NT];     // emission features
__device__ unsigned long long g_flagq[2][32];  // 64 per-CTA step flags per dir

// ---------------------------------------------------------------------------
__global__ void zero_flags_kernel() {
    int i = threadIdx.x;
    if (i < 64) ((unsigned long long*)g_flagq)[i] = 0ull;
}

// ---------------- xproj GEMM: C[t][row] = x[t] . Wih[row] + b[row] ---------
// BM=BN=128, BK=16, 256 threads, 8x8 microtile
__global__ void __launch_bounds__(256) xproj_kernel(
    const int* __restrict__ sentence, const float* __restrict__ emb,
    const float* __restrict__ wih_f, const float* __restrict__ b_f,
    const float* __restrict__ wih_b, const float* __restrict__ b_b)
{
    __shared__ float As[16][128];
    __shared__ float Bs[16][128];

    const int dir = blockIdx.z;
    const float* __restrict__ wih  = dir ? wih_b : wih_f;
    const float* __restrict__ bias = dir ? b_b  : b_f;
    const int m0 = blockIdx.y * 128;   // t tile
    const int n0 = blockIdx.x * 128;   // gate-row tile
    const int tid = threadIdx.x;

    const int lr = tid >> 1;           // 0..127
    const int lk = (tid & 1) * 8;      // 0 or 8
    const float* arow = emb + (size_t)sentence[m0 + lr] * E + lk;
    const float* brow = wih + (size_t)(n0 + lr) * E + lk;

    const int tx = tid & 15, ty = tid >> 4;
    float acc[8][8];
#pragma unroll
    for (int i = 0; i < 8; i++)
#pragma unroll
        for (int j = 0; j < 8; j++) acc[i][j] = 0.f;

    for (int k0 = 0; k0 < E; k0 += 16) {
        float4 a0 = *(const float4*)(arow + k0);
        float4 a1 = *(const float4*)(arow + k0 + 4);
        float4 b0 = *(const float4*)(brow + k0);
        float4 b1 = *(const float4*)(brow + k0 + 4);
        __syncthreads();
        As[lk + 0][lr] = a0.x; As[lk + 1][lr] = a0.y; As[lk + 2][lr] = a0.z; As[lk + 3][lr] = a0.w;
        As[lk + 4][lr] = a1.x; As[lk + 5][lr] = a1.y; As[lk + 6][lr] = a1.z; As[lk + 7][lr] = a1.w;
        Bs[lk + 0][lr] = b0.x; Bs[lk + 1][lr] = b0.y; Bs[lk + 2][lr] = b0.z; Bs[lk + 3][lr] = b0.w;
        Bs[lk + 4][lr] = b1.x; Bs[lk + 5][lr] = b1.y; Bs[lk + 6][lr] = b1.z; Bs[lk + 7][lr] = b1.w;
        __syncthreads();
#pragma unroll
        for (int kk = 0; kk < 16; kk++) {
            float a[8], b[8];
            *(float4*)&a[0] = *(const float4*)&As[kk][ty * 8];
            *(float4*)&a[4] = *(const float4*)&As[kk][ty * 8 + 4];
            *(float4*)&b[0] = *(const float4*)&Bs[kk][tx * 8];
            *(float4*)&b[4] = *(const float4*)&Bs[kk][tx * 8 + 4];
#pragma unroll
            for (int i = 0; i < 8; i++)
#pragma unroll
                for (int j = 0; j < 8; j++)
                    acc[i][j] = fmaf(a[i], b[j], acc[i][j]);
        }
    }

    float bv[8];
#pragma unroll
    for (int j = 0; j < 8; j++) bv[j] = bias[n0 + tx * 8 + j];
#pragma unroll
    for (int i = 0; i < 8; i++) {
        const int m = m0 + ty * 8 + i;
        float4 o0, o1;
        o0.x = acc[i][0] + bv[0]; o0.y = acc[i][1] + bv[1];
        o0.z = acc[i][2] + bv[2]; o0.w = acc[i][3] + bv[3];
        o1.x = acc[i][4] + bv[4]; o1.y = acc[i][5] + bv[5];
        o1.z = acc[i][6] + bv[6]; o1.w = acc[i][7] + bv[7];
        *(float4*)&g_xp[dir][m][n0 + tx * 8]     = o0;
        *(float4*)&g_xp[dir][m][n0 + tx * 8 + 4] = o1;
    }
}

// ---------------- persistent bidirectional LSTM ----------------------------
// grid = 128 CTAs (64/dir), 256 threads (8 warps). warp w owns h-index
// cid*8+w; each lane holds 4x16 Whh weights in registers.
// Sync: per-CTA flag (step number) via st.release; consumers poll 64 flags
// with ld.acquire.b64 (one per lane) + __all_sync. No atomics.
__device__ __forceinline__ float sigmoid_f(float x) {
    return __fdividef(1.0f, 1.0f + __expf(-x));
}
__device__ __forceinline__ float tanh_f(float x) {
    return 1.0f - 2.0f * __fdividef(1.0f, 1.0f + __expf(2.0f * x));
}

__global__ void __launch_bounds__(256, 1) lstm_kernel(
    const float* __restrict__ whh_f, const float* __restrict__ whh_b,
    const float* __restrict__ h0, const float* __restrict__ c0)
{
    const int dir  = blockIdx.x & 1;
    const int cid  = blockIdx.x >> 1;          // 0..63
    const int warp = threadIdx.x >> 5;         // 0..7
    const int lane = threadIdx.x & 31;
    const int tid  = threadIdx.x;
    const int hidx = cid * 8 + warp;           // 0..511

    __shared__ float sh[HD];                   // staged h (2KB)

    const float* __restrict__ whh = dir ? whh_b : whh_f;

    float wr[4][16];
#pragma unroll
    for (int gg = 0; gg < 4; gg++) {
        const float* r = whh + (size_t)(gg * HD + hidx) * HD + lane * 16;
#pragma unroll
        for (int q = 0; q < 4; q++) {
            float4 v = *(const float4*)(r + q * 4);
            wr[gg][q * 4 + 0] = v.x; wr[gg][q * 4 + 1] = v.y;
            wr[gg][q * 4 + 2] = v.z; wr[gg][q * 4 + 3] = v.w;
        }
    }
    float c = c0[dir * HD + hidx];   // replicated on all lanes

    int* myflag = &((int*)g_flagq)[dir * 64 + cid];
    const unsigned long long* fq = &g_flagq[dir][lane];

    int t = dir ? (S - 1) : 0;
    const int dt = dir ? -1 : 1;

    for (int s = 0; s < S; s++, t += dt) {
        // prefetch this lane's gate pre-activation (lane k<4 -> gate k)
        float xv = 0.0f;
        if (lane < 4) xv = g_xp[dir][t][lane * HD + hidx];

        const float* hp;
        if (s == 0) {
            hp = h0 + dir * HD;
        } else {
            const int tp = t - dt;
            // poll 64 flags (2 per lane via one b64 acquire load)
            unsigned long long q;
            int ok;
            do {
                asm volatile("ld.acquire.gpu.global.b64 %0, [%1];"
                             : "=l"(q) : "l"(fq) : "memory");
                ok = ((int)(q & 0xFFFFFFFFull) >= s) && ((int)(q >> 32) >= s);
            } while (!__all_sync(0xFFFFFFFFu, ok));
            hp = &g_hs[dir][tp][0];
        }

        // stage h into SMEM (256 threads x float2), then read strided
        float2 hv2 = ((const float2*)hp)[tid];
        sh[2 * tid]     = hv2.x;
        sh[2 * tid + 1] = hv2.y;
        __syncthreads();

        float hv[16];
#pragma unroll
        for (int q = 0; q < 4; q++) {
            float4 v = *(const float4*)&sh[lane * 16 + q * 4];
            hv[q * 4 + 0] = v.x; hv[q * 4 + 1] = v.y;
            hv[q * 4 + 2] = v.z; hv[q * 4 + 3] = v.w;
        }

        float a0 = 0.f, a1 = 0.f, a2 = 0.f, a3 = 0.f;
#pragma unroll
        for (int k = 0; k < 16; k++) {
            a0 = fmaf(hv[k], wr[0][k], a0);
            a1 = fmaf(hv[k], wr[1][k], a1);
            a2 = fmaf(hv[k], wr[2][k], a2);
            a3 = fmaf(hv[k], wr[3][k], a3);
        }
#pragma unroll
        for (int off = 16; off > 0; off >>= 1) {
            a0 += __shfl_xor_sync(0xFFFFFFFFu, a0, off);
            a1 += __shfl_xor_sync(0xFFFFFFFFu, a1, off);
            a2 += __shfl_xor_sync(0xFFFFFFFFu, a2, off);
            a3 += __shfl_xor_sync(0xFFFFFFFFu, a3, off);
        }

        // gates distributed: lane k (k<4) computes activation of gate k
        const float pre = ((lane == 0) ? a0 : (lane == 1) ? a1
                          : (lane == 2) ? a2 : a3) + xv;
        const float sg = sigmoid_f(pre);
        const float th = tanh_f(pre);
        const float act = (lane == 2) ? th : sg;

        const float ig = __shfl_sync(0xFFFFFFFFu, act, 0);
        const float fg = __shfl_sync(0xFFFFFFFFu, act, 1);
        const float tg = __shfl_sync(0xFFFFFFFFu, act, 2);
        const float og = __shfl_sync(0xFFFFFFFFu, act, 3);

        c = fg * c + ig * tg;                 // replicated on all lanes
        const float hvout = og * tanh_f(c);
        if (lane == 0) g_hs[dir][t][hidx] = hvout;

        __syncthreads();                      // order h stores + protect sh reuse
        if (tid == 0) {
            asm volatile("st.release.gpu.global.b32 [%0], %1;"
                         :: "l"(myflag), "r"(s + 1) : "memory");
        }
    }
}

// ---------------- feats: [S, NT] = [hf|hb] @ w_out^T + b_out ---------------
__global__ void feats_kernel(const float* __restrict__ w_out,
                             const float* __restrict__ b_out)
{
    const int t = blockIdx.x;
    const int tid = threadIdx.x;   // 128
    float par[NT];
#pragma unroll
    for (int g = 0; g < NT; g++) par[g] = 0.f;

    for (int j = tid; j < HD; j += 128) {
        const float hf = g_hs[0][t][j];
        const float hb = g_hs[1][t][j];
#pragma unroll
        for (int g = 0; g < NT; g++)
            par[g] += hf * w_out[g * 1024 + j] + hb * w_out[g * 1024 + HD + j];
    }
#pragma unroll
    for (int off = 16; off > 0; off >>= 1)
#pragma unroll
        for (int g = 0; g < NT; g++)
            par[g] += __shfl_xor_sync(0xFFFFFFFFu, par[g], off);

    __shared__ float sm[NT][4];
    if ((tid & 31) == 0)
#pragma unroll
        for (int g = 0; g < NT; g++) sm[g][tid >> 5] = par[g];
    __syncthreads();
    if (tid < NT)
        g_feats[t][tid] = sm[tid][0] + sm[tid][1] + sm[tid][2] + sm[tid][3] + b_out[tid];
}

// ---------------- CRF: forward scan + gold score ---------------------------
// warp0: lane i owns tag i. Factorized: E_ij = exp(tr_ij) precomputed once;
// per step only exp(prev) (1 MUFU) + gather + log. Rebase each step by live
// lane 2's value (single shuffle); offset accumulated in double.
// warp1: gold path score (double accumulation)
__global__ void crf_kernel(const float* __restrict__ trans,
                           const int* __restrict__ gold_tags,
                           float* __restrict__ out)
{
    const int tid = threadIdx.x;    // 64 threads
    __shared__ double s_gold;
    __shared__ double s_alpha;

    if (tid >= 32) {
        // gold score
        const int lane = tid - 32;
        double acc = 0.0;
        for (int t = lane; t < S; t += 32) {
            const int tc = gold_tags[t];
            const int tp = (t == 0) ? 0 /*START*/ : gold_tags[t - 1];
            acc += (double)trans[tc * NT + tp] + (double)g_feats[t][tc];
        }
#pragma unroll
        for (int off = 16; off > 0; off >>= 1)
            acc += __shfl_xor_sync(0xFFFFFFFFu, acc, off);
        if (lane == 0)
            s_gold = acc + (double)trans[1 * NT + gold_tags[S - 1]];  // END=1
    } else {
        const int i = tid;
        const bool act = (i < NT);
        float Erow[NT];
#pragma unroll
        for (int j = 0; j < NT; j++)
            Erow[j] = act ? __expf(trans[i * NT + j]) : 0.0f;

        // init alphas: START(lane0)=0, other live tags -1e6, inactive -inf-ish
        float prev = act ? ((i == 0) ? 0.f : -1e6f) : -3.0e38f;
        double base = 0.0;
        float fnext = act ? g_feats[0][i] : 0.f;

        for (int t = 0; t < S; t++) {
            const float feat = fnext;
            if (t + 1 < S) fnext = act ? g_feats[t + 1][i] : 0.f;

            const float e = __expf(prev);        // <=0-ish after rebase
            float s0 = 0.f, s1 = 0.f, s2 = 0.f;
#pragma unroll
            for (int j = 0; j < 4; j++) {
                s0 = fmaf(__shfl_sync(0xFFFFFFFFu, e, j),     Erow[j],     s0);
                s1 = fmaf(__shfl_sync(0xFFFFFFFFu, e, j + 4), Erow[j + 4], s1);
                s2 = fmaf(__shfl_sync(0xFFFFFFFFu, e, j + 8), Erow[j + 8], s2);
            }
            const float pn = feat + __logf(s0 + s1 + s2);   // -inf ok
            const float d = __shfl_sync(0xFFFFFFFFu, pn, 2); // live tag ref
            base += (double)d;
            prev = act ? (pn - d) : -3.0e38f;
        }
        // alpha = base + logsumexp_i(prev_i + trans[END=1][i])
        float fv = act ? (prev + trans[1 * NT + i]) : -3.0e38f;
        float m = fv;
#pragma unroll
        for (int off = 16; off > 0; off >>= 1)
            m = fmaxf(m, __shfl_xor_sync(0xFFFFFFFFu, m, off));
        float e = act ? __expf(fv - m) : 0.f;
#pragma unroll
        for (int off = 16; off > 0; off >>= 1)
            e += __shfl_xor_sync(0xFFFFFFFFu, e, off);
        if (tid == 0)
            s_alpha = base + (double)m + log((double)e);
    }
    __syncthreads();
    if (tid == 0)
        out[0] = (float)(s_alpha - s_gold);
}

// ---------------------------------------------------------------------------
extern "C" void kernel_launch(void* const* d_in, const int* in_sizes, int n_in,
                              void* d_out, int out_size)
{
    const int*   sentence = (const int*)  d_in[0];
    const int*   gold     = (const int*)  d_in[1];
    const float* emb      = (const float*)d_in[2];
    const float* wih_f    = (const float*)d_in[3];
    const float* whh_f    = (const float*)d_in[4];
    const float* b_f      = (const float*)d_in[5];
    const float* wih_b    = (const float*)d_in[6];
    const float* whh_b    = (const float*)d_in[7];
    const float* b_b      = (const float*)d_in[8];
    const float* w_out    = (const float*)d_in[9];
    const float* b_out    = (const float*)d_in[10];
    const float* trans    = (const float*)d_in[11];
    const float* h0       = (const float*)d_in[12];
    const float* c0       = (const float*)d_in[13];
    float* out = (float*)d_out;

    zero_flags_kernel<<<1, 64>>>();

    dim3 gg(G4 / 128, S / 128, 2);
    xproj_kernel<<<gg, 256>>>(sentence, emb, wih_f, b_f, wih_b, b_b);

    lstm_kernel<<<128, 256>>>(whh_f, whh_b, h0, c0);

    feats_kernel<<<S, 128>>>(w_out, b_out);

    crf_kernel<<<1, 64>>>(trans, gold, out);
}

// round 8
// speedup vs baseline: 1.1416x; 1.1416x over previous
#include <cuda_runtime.h>
#include <math.h>

#define S 2048
#define E 512
#define HD 512
#define G4 2048   /* 4*HD */
#define NT 12     /* tags */
#define NCTA 32   /* CTAs per direction */

// ---------------- scratch (device globals; no runtime allocation) ----------
__device__ float g_xp[2][S][G4];     // input projections + bias, both dirs (32 MB)
__device__ float g_hs[2][S][HD];     // hidden states, both dirs (8 MB)
__device__ float g_feats[S][NT];     // emission features
__device__ int   g_flag[2][NCTA];    // per-CTA step flags: one 128B line per dir

// ---------------------------------------------------------------------------
__global__ void zero_flags_kernel() {
    int i = threadIdx.x;
    if (i < 2 * NCTA) ((int*)g_flag)[i] = 0;
}

// ---------------- xproj GEMM: C[t][row] = x[t] . Wih[row] + b[row] ---------
// BM=BN=128, BK=16, 256 threads, 8x8 microtile
__global__ void __launch_bounds__(256) xproj_kernel(
    const int* __restrict__ sentence, const float* __restrict__ emb,
    const float* __restrict__ wih_f, const float* __restrict__ b_f,
    const float* __restrict__ wih_b, const float* __restrict__ b_b)
{
    __shared__ float As[16][128];
    __shared__ float Bs[16][128];

    const int dir = blockIdx.z;
    const float* __restrict__ wih  = dir ? wih_b : wih_f;
    const float* __restrict__ bias = dir ? b_b  : b_f;
    const int m0 = blockIdx.y * 128;   // t tile
    const int n0 = blockIdx.x * 128;   // gate-row tile
    const int tid = threadIdx.x;

    const int lr = tid >> 1;           // 0..127
    const int lk = (tid & 1) * 8;      // 0 or 8
    const float* arow = emb + (size_t)sentence[m0 + lr] * E + lk;
    const float* brow = wih + (size_t)(n0 + lr) * E + lk;

    const int tx = tid & 15, ty = tid >> 4;
    float acc[8][8];
#pragma unroll
    for (int i = 0; i < 8; i++)
#pragma unroll
        for (int j = 0; j < 8; j++) acc[i][j] = 0.f;

    for (int k0 = 0; k0 < E; k0 += 16) {
        float4 a0 = *(const float4*)(arow + k0);
        float4 a1 = *(const float4*)(arow + k0 + 4);
        float4 b0 = *(const float4*)(brow + k0);
        float4 b1 = *(const float4*)(brow + k0 + 4);
        __syncthreads();
        As[lk + 0][lr] = a0.x; As[lk + 1][lr] = a0.y; As[lk + 2][lr] = a0.z; As[lk + 3][lr] = a0.w;
        As[lk + 4][lr] = a1.x; As[lk + 5][lr] = a1.y; As[lk + 6][lr] = a1.z; As[lk + 7][lr] = a1.w;
        Bs[lk + 0][lr] = b0.x; Bs[lk + 1][lr] = b0.y; Bs[lk + 2][lr] = b0.z; Bs[lk + 3][lr] = b0.w;
        Bs[lk + 4][lr] = b1.x; Bs[lk + 5][lr] = b1.y; Bs[lk + 6][lr] = b1.z; Bs[lk + 7][lr] = b1.w;
        __syncthreads();
#pragma unroll
        for (int kk = 0; kk < 16; kk++) {
            float a[8], b[8];
            *(float4*)&a[0] = *(const float4*)&As[kk][ty * 8];
            *(float4*)&a[4] = *(const float4*)&As[kk][ty * 8 + 4];
            *(float4*)&b[0] = *(const float4*)&Bs[kk][tx * 8];
            *(float4*)&b[4] = *(const float4*)&Bs[kk][tx * 8 + 4];
#pragma unroll
            for (int i = 0; i < 8; i++)
#pragma unroll
                for (int j = 0; j < 8; j++)
                    acc[i][j] = fmaf(a[i], b[j], acc[i][j]);
        }
    }

    float bv[8];
#pragma unroll
    for (int j = 0; j < 8; j++) bv[j] = bias[n0 + tx * 8 + j];
#pragma unroll
    for (int i = 0; i < 8; i++) {
        const int m = m0 + ty * 8 + i;
        float4 o0, o1;
        o0.x = acc[i][0] + bv[0]; o0.y = acc[i][1] + bv[1];
        o0.z = acc[i][2] + bv[2]; o0.w = acc[i][3] + bv[3];
        o1.x = acc[i][4] + bv[4]; o1.y = acc[i][5] + bv[5];
        o1.z = acc[i][6] + bv[6]; o1.w = acc[i][7] + bv[7];
        *(float4*)&g_xp[dir][m][n0 + tx * 8]     = o0;
        *(float4*)&g_xp[dir][m][n0 + tx * 8 + 4] = o1;
    }
}

// ---------------- persistent bidirectional LSTM ----------------------------
// grid = 64 CTAs (32/dir), 512 threads (16 warps). warp w owns h-index
// cid*16+w; each lane holds 4x16 Whh weights in registers.
// Sync: per-CTA flag (step number) via st.release to DISTINCT addresses in
// ONE 128B line per direction; consumers poll with one lane-per-flag
// ld.acquire.b32 (single line per warp poll) + __all_sync.
__device__ __forceinline__ float sigmoid_f(float x) {
    return __fdividef(1.0f, 1.0f + __expf(-x));
}
__device__ __forceinline__ float tanh_f(float x) {
    return 1.0f - 2.0f * __fdividef(1.0f, 1.0f + __expf(2.0f * x));
}

__global__ void __launch_bounds__(512, 1) lstm_kernel(
    const float* __restrict__ whh_f, const float* __restrict__ whh_b,
    const float* __restrict__ h0, const float* __restrict__ c0)
{
    const int dir  = blockIdx.x & 1;
    const int cid  = blockIdx.x >> 1;          // 0..31
    const int warp = threadIdx.x >> 5;         // 0..15
    const int lane = threadIdx.x & 31;
    const int tid  = threadIdx.x;
    const int hidx = cid * 16 + warp;          // 0..511

    __shared__ float sh[HD];                   // staged h (2KB)

    const float* __restrict__ whh = dir ? whh_b : whh_f;

    float wr[4][16];
#pragma unroll
    for (int gg = 0; gg < 4; gg++) {
        const float* r = whh + (size_t)(gg * HD + hidx) * HD + lane * 16;
#pragma unroll
        for (int q = 0; q < 4; q++) {
            float4 v = *(const float4*)(r + q * 4);
            wr[gg][q * 4 + 0] = v.x; wr[gg][q * 4 + 1] = v.y;
            wr[gg][q * 4 + 2] = v.z; wr[gg][q * 4 + 3] = v.w;
        }
    }
    float c = c0[dir * HD + hidx];   // replicated on all lanes

    int* myflag = &g_flag[dir][cid];
    const int* fq = &g_flag[dir][lane];   // lane i watches CTA i's flag

    int t = dir ? (S - 1) : 0;
    const int dt = dir ? -1 : 1;

    for (int s = 0; s < S; s++, t += dt) {
        // prefetch this lane's gate pre-activation (lane k<4 -> gate k)
        float xv = 0.0f;
        if (lane < 4) xv = g_xp[dir][t][lane * HD + hidx];

        const float* hp;
        if (s == 0) {
            hp = h0 + dir * HD;
        } else {
            const int tp = t - dt;
            // poll 32 flags: lane i checks flag i -> ONE 128B line per iter
            int v, ok;
            do {
                asm volatile("ld.acquire.gpu.global.b32 %0, [%1];"
                             : "=r"(v) : "l"(fq) : "memory");
                ok = (v >= s);
            } while (!__all_sync(0xFFFFFFFFu, ok));
            hp = &g_hs[dir][tp][0];
        }

        // stage h into SMEM (512 threads x 1 float), then read via LDS
        sh[tid] = hp[tid];
        __syncthreads();

        float hv[16];
#pragma unroll
        for (int q = 0; q < 4; q++) {
            float4 v = *(const float4*)&sh[lane * 16 + q * 4];
            hv[q * 4 + 0] = v.x; hv[q * 4 + 1] = v.y;
            hv[q * 4 + 2] = v.z; hv[q * 4 + 3] = v.w;
        }

        float a0 = 0.f, a1 = 0.f, a2 = 0.f, a3 = 0.f;
#pragma unroll
        for (int k = 0; k < 16; k++) {
            a0 = fmaf(hv[k], wr[0][k], a0);
            a1 = fmaf(hv[k], wr[1][k], a1);
            a2 = fmaf(hv[k], wr[2][k], a2);
            a3 = fmaf(hv[k], wr[3][k], a3);
        }
#pragma unroll
        for (int off = 16; off > 0; off >>= 1) {
            a0 += __shfl_xor_sync(0xFFFFFFFFu, a0, off);
            a1 += __shfl_xor_sync(0xFFFFFFFFu, a1, off);
            a2 += __shfl_xor_sync(0xFFFFFFFFu, a2, off);
            a3 += __shfl_xor_sync(0xFFFFFFFFu, a3, off);
        }

        // gates distributed: lane k (k<4) computes activation of gate k
        const float pre = ((lane == 0) ? a0 : (lane == 1) ? a1
                          : (lane == 2) ? a2 : a3) + xv;
        const float sg = sigmoid_f(pre);
        const float th = tanh_f(pre);
        const float act = (lane == 2) ? th : sg;

        const float ig = __shfl_sync(0xFFFFFFFFu, act, 0);
        const float fg = __shfl_sync(0xFFFFFFFFu, act, 1);
        const float tg = __shfl_sync(0xFFFFFFFFu, act, 2);
        const float og = __shfl_sync(0xFFFFFFFFu, act, 3);

        c = fg * c + ig * tg;                 // replicated on all lanes
        const float hvout = og * tanh_f(c);
        if (lane == 0) g_hs[dir][t][hidx] = hvout;

        __syncthreads();                      // order h stores + protect sh reuse
        if (tid == 0) {
            asm volatile("st.release.gpu.global.b32 [%0], %1;"
                         :: "l"(myflag), "r"(s + 1) : "memory");
        }
    }
}

// ---------------- feats: [S, NT] = [hf|hb] @ w_out^T + b_out ---------------
__global__ void feats_kernel(const float* __restrict__ w_out,
                             const float* __restrict__ b_out)
{
    const int t = blockIdx.x;
    const int tid = threadIdx.x;   // 128
    float par[NT];
#pragma unroll
    for (int g = 0; g < NT; g++) par[g] = 0.f;

    for (int j = tid; j < HD; j += 128) {
        const float hf = g_hs[0][t][j];
        const float hb = g_hs[1][t][j];
#pragma unroll
        for (int g = 0; g < NT; g++)
            par[g] += hf * w_out[g * 1024 + j] + hb * w_out[g * 1024 + HD + j];
    }
#pragma unroll
    for (int off = 16; off > 0; off >>= 1)
#pragma unroll
        for (int g = 0; g < NT; g++)
            par[g] += __shfl_xor_sync(0xFFFFFFFFu, par[g], off);

    __shared__ float sm[NT][4];
    if ((tid & 31) == 0)
#pragma unroll
        for (int g = 0; g < NT; g++) sm[g][tid >> 5] = par[g];
    __syncthreads();
    if (tid < NT)
        g_feats[t][tid] = sm[tid][0] + sm[tid][1] + sm[tid][2] + sm[tid][3] + b_out[tid];
}

// ---------------- CRF: forward scan + gold score ---------------------------
// warp0: lane i owns tag i. Factorized: E_ij = exp(tr_ij) precomputed once;
// per step only exp(prev) (1 MUFU) + gather + log. Rebase each step by live
// lane 2's value (single shuffle); offset accumulated in double.
// warp1: gold path score (double accumulation)
__global__ void crf_kernel(const float* __restrict__ trans,
                           const int* __restrict__ gold_tags,
                           float* __restrict__ out)
{
    const int tid = threadIdx.x;    // 64 threads
    __shared__ double s_gold;
    __shared__ double s_alpha;

    if (tid >= 32) {
        // gold score
        const int lane = tid - 32;
        double acc = 0.0;
        for (int t = lane; t < S; t += 32) {
            const int tc = gold_tags[t];
            const int tp = (t == 0) ? 0 /*START*/ : gold_tags[t - 1];
            acc += (double)trans[tc * NT + tp] + (double)g_feats[t][tc];
        }
#pragma unroll
        for (int off = 16; off > 0; off >>= 1)
            acc += __shfl_xor_sync(0xFFFFFFFFu, acc, off);
        if (lane == 0)
            s_gold = acc + (double)trans[1 * NT + gold_tags[S - 1]];  // END=1
    } else {
        const int i = tid;
        const bool act = (i < NT);
        float Erow[NT];
#pragma unroll
        for (int j = 0; j < NT; j++)
            Erow[j] = act ? __expf(trans[i * NT + j]) : 0.0f;

        // init alphas: START(lane0)=0, other live tags -1e6, inactive -inf-ish
        float prev = act ? ((i == 0) ? 0.f : -1e6f) : -3.0e38f;
        double base = 0.0;
        float fnext = act ? g_feats[0][i] : 0.f;

        for (int t = 0; t < S; t++) {
            const float feat = fnext;
            if (t + 1 < S) fnext = act ? g_feats[t + 1][i] : 0.f;

            const float e = __expf(prev);        // small after rebase
            float s0 = 0.f, s1 = 0.f, s2 = 0.f;
#pragma unroll
            for (int j = 0; j < 4; j++) {
                s0 = fmaf(__shfl_sync(0xFFFFFFFFu, e, j),     Erow[j],     s0);
                s1 = fmaf(__shfl_sync(0xFFFFFFFFu, e, j + 4), Erow[j + 4], s1);
                s2 = fmaf(__shfl_sync(0xFFFFFFFFu, e, j + 8), Erow[j + 8], s2);
            }
            const float pn = feat + __logf(s0 + s1 + s2);   // -inf ok
            const float d = __shfl_sync(0xFFFFFFFFu, pn, 2); // live tag ref
            base += (double)d;
            prev = act ? (pn - d) : -3.0e38f;
        }
        // alpha = base + logsumexp_i(prev_i + trans[END=1][i])
        float fv = act ? (prev + trans[1 * NT + i]) : -3.0e38f;
        float m = fv;
#pragma unroll
        for (int off = 16; off > 0; off >>= 1)
            m = fmaxf(m, __shfl_xor_sync(0xFFFFFFFFu, m, off));
        float e = act ? __expf(fv - m) : 0.f;
#pragma unroll
        for (int off = 16; off > 0; off >>= 1)
            e += __shfl_xor_sync(0xFFFFFFFFu, e, off);
        if (tid == 0)
            s_alpha = base + (double)m + log((double)e);
    }
    __syncthreads();
    if (tid == 0)
        out[0] = (float)(s_alpha - s_gold);
}

// ---------------------------------------------------------------------------
extern "C" void kernel_launch(void* const* d_in, const int* in_sizes, int n_in,
                              void* d_out, int out_size)
{
    const int*   sentence = (const int*)  d_in[0];
    const int*   gold     = (const int*)  d_in[1];
    const float* emb      = (const float*)d_in[2];
    const float* wih_f    = (const float*)d_in[3];
    const float* whh_f    = (const float*)d_in[4];
    const float* b_f      = (const float*)d_in[5];
    const float* wih_b    = (const float*)d_in[6];
    const float* whh_b    = (const float*)d_in[7];
    const float* b_b      = (const float*)d_in[8];
    const float* w_out    = (const float*)d_in[9];
    const float* b_out    = (const float*)d_in[10];
    const float* trans    = (const float*)d_in[11];
    const float* h0       = (const float*)d_in[12];
    const float* c0       = (const float*)d_in[13];
    float* out = (float*)d_out;

    zero_flags_kernel<<<1, 64>>>();

    dim3 gg(G4 / 128, S / 128, 2);
    xproj_kernel<<<gg, 256>>>(sentence, emb, wih_f, b_f, wih_b, b_b);

    lstm_kernel<<<64, 512>>>(whh_f, whh_b, h0, c0);

    feats_kernel<<<S, 128>>>(w_out, b_out);

    crf_kernel<<<1, 64>>>(trans, gold, out);
}

// round 9
// speedup vs baseline: 2.8752x; 2.5186x over previous
#include <cuda_runtime.h>
#include <math.h>

#define S 2048
#define E 512
#define HD 512
#define G4 2048   /* 4*HD */
#define NT 12     /* tags */
#define NCTA 32   /* CTAs per direction */

// ---------------- scratch (device globals; no runtime allocation) ----------
__device__ float g_xp[2][S][G4];     // input projections + bias, both dirs (32 MB)
__device__ float g_hs[2][S][HD];     // hidden states, both dirs (8 MB)
__device__ float g_feats[S][NT];     // emission features
__device__ __align__(128) int g_flag[2][NCTA];  // per-CTA step flags (1 line/dir)

// ---------------------------------------------------------------------------
__global__ void zero_flags_kernel() {
    int i = threadIdx.x;
    if (i < 2 * NCTA) ((int*)g_flag)[i] = 0;
}

// ---------------- xproj GEMM: C[t][row] = x[t] . Wih[row] + b[row] ---------
// BM=BN=128, BK=16, 256 threads, 8x8 microtile
__global__ void __launch_bounds__(256) xproj_kernel(
    const int* __restrict__ sentence, const float* __restrict__ emb,
    const float* __restrict__ wih_f, const float* __restrict__ b_f,
    const float* __restrict__ wih_b, const float* __restrict__ b_b)
{
    __shared__ float As[16][128];
    __shared__ float Bs[16][128];

    const int dir = blockIdx.z;
    const float* __restrict__ wih  = dir ? wih_b : wih_f;
    const float* __restrict__ bias = dir ? b_b  : b_f;
    const int m0 = blockIdx.y * 128;   // t tile
    const int n0 = blockIdx.x * 128;   // gate-row tile
    const int tid = threadIdx.x;

    const int lr = tid >> 1;           // 0..127
    const int lk = (tid & 1) * 8;      // 0 or 8
    const float* arow = emb + (size_t)sentence[m0 + lr] * E + lk;
    const float* brow = wih + (size_t)(n0 + lr) * E + lk;

    const int tx = tid & 15, ty = tid >> 4;
    float acc[8][8];
#pragma unroll
    for (int i = 0; i < 8; i++)
#pragma unroll
        for (int j = 0; j < 8; j++) acc[i][j] = 0.f;

    for (int k0 = 0; k0 < E; k0 += 16) {
        float4 a0 = *(const float4*)(arow + k0);
        float4 a1 = *(const float4*)(arow + k0 + 4);
        float4 b0 = *(const float4*)(brow + k0);
        float4 b1 = *(const float4*)(brow + k0 + 4);
        __syncthreads();
        As[lk + 0][lr] = a0.x; As[lk + 1][lr] = a0.y; As[lk + 2][lr] = a0.z; As[lk + 3][lr] = a0.w;
        As[lk + 4][lr] = a1.x; As[lk + 5][lr] = a1.y; As[lk + 6][lr] = a1.z; As[lk + 7][lr] = a1.w;
        Bs[lk + 0][lr] = b0.x; Bs[lk + 1][lr] = b0.y; Bs[lk + 2][lr] = b0.z; Bs[lk + 3][lr] = b0.w;
        Bs[lk + 4][lr] = b1.x; Bs[lk + 5][lr] = b1.y; Bs[lk + 6][lr] = b1.z; Bs[lk + 7][lr] = b1.w;
        __syncthreads();
#pragma unroll
        for (int kk = 0; kk < 16; kk++) {
            float a[8], b[8];
            *(float4*)&a[0] = *(const float4*)&As[kk][ty * 8];
            *(float4*)&a[4] = *(const float4*)&As[kk][ty * 8 + 4];
            *(float4*)&b[0] = *(const float4*)&Bs[kk][tx * 8];
            *(float4*)&b[4] = *(const float4*)&Bs[kk][tx * 8 + 4];
#pragma unroll
            for (int i = 0; i < 8; i++)
#pragma unroll
                for (int j = 0; j < 8; j++)
                    acc[i][j] = fmaf(a[i], b[j], acc[i][j]);
        }
    }

    float bv[8];
#pragma unroll
    for (int j = 0; j < 8; j++) bv[j] = bias[n0 + tx * 8 + j];
#pragma unroll
    for (int i = 0; i < 8; i++) {
        const int m = m0 + ty * 8 + i;
        float4 o0, o1;
        o0.x = acc[i][0] + bv[0]; o0.y = acc[i][1] + bv[1];
        o0.z = acc[i][2] + bv[2]; o0.w = acc[i][3] + bv[3];
        o1.x = acc[i][4] + bv[4]; o1.y = acc[i][5] + bv[5];
        o1.z = acc[i][6] + bv[6]; o1.w = acc[i][7] + bv[7];
        *(float4*)&g_xp[dir][m][n0 + tx * 8]     = o0;
        *(float4*)&g_xp[dir][m][n0 + tx * 8 + 4] = o1;
    }
}

// ---------------- persistent bidirectional LSTM ----------------------------
// grid = 64 CTAs (32/dir), 512 threads (16 warps). warp w owns h-index
// cid*16+w; each lane holds 4x16 Whh weights in registers.
// Sync: arrival = per-CTA st.release to DISTINCT 4B slots in one 128B
// line/dir. Wait = ONLY WARP 0 polls (lane i watches flag i, one line per
// poll iter -> 64 polling warps chip-wide, LTS slice stays unsaturated),
// then bar.sync releases the CTA.
__device__ __forceinline__ float sigmoid_f(float x) {
    return __fdividef(1.0f, 1.0f + __expf(-x));
}
__device__ __forceinline__ float tanh_f(float x) {
    return 1.0f - 2.0f * __fdividef(1.0f, 1.0f + __expf(2.0f * x));
}

__global__ void __launch_bounds__(512, 1) lstm_kernel(
    const float* __restrict__ whh_f, const float* __restrict__ whh_b,
    const float* __restrict__ h0, const float* __restrict__ c0)
{
    const int dir  = blockIdx.x & 1;
    const int cid  = blockIdx.x >> 1;          // 0..31
    const int warp = threadIdx.x >> 5;         // 0..15
    const int lane = threadIdx.x & 31;
    const int tid  = threadIdx.x;
    const int hidx = cid * 16 + warp;          // 0..511

    __shared__ float sh[HD];                   // staged h (2KB)

    const float* __restrict__ whh = dir ? whh_b : whh_f;

    float wr[4][16];
#pragma unroll
    for (int gg = 0; gg < 4; gg++) {
        const float* r = whh + (size_t)(gg * HD + hidx) * HD + lane * 16;
#pragma unroll
        for (int q = 0; q < 4; q++) {
            float4 v = *(const float4*)(r + q * 4);
            wr[gg][q * 4 + 0] = v.x; wr[gg][q * 4 + 1] = v.y;
            wr[gg][q * 4 + 2] = v.z; wr[gg][q * 4 + 3] = v.w;
        }
    }
    float c = c0[dir * HD + hidx];   // replicated on all lanes

    int* myflag = &g_flag[dir][cid];
    const int* fq = &g_flag[dir][lane];   // lane i watches CTA i's flag

    int t = dir ? (S - 1) : 0;
    const int dt = dir ? -1 : 1;

    for (int s = 0; s < S; s++, t += dt) {
        // prefetch this lane's gate pre-activation (lane k<4 -> gate k)
        float xv = 0.0f;
        if (lane < 4) xv = g_xp[dir][t][lane * HD + hidx];

        const float* hp;
        if (s == 0) {
            hp = h0 + dir * HD;
        } else {
            hp = &g_hs[dir][t - dt][0];
            // only warp 0 polls; CTA released by bar.sync
            if (warp == 0) {
                int v, ok;
                do {
                    asm volatile("ld.acquire.gpu.global.b32 %0, [%1];"
                                 : "=r"(v) : "l"(fq) : "memory");
                    ok = (v >= s);
                } while (!__all_sync(0xFFFFFFFFu, ok));
            }
            __syncthreads();
        }

        // stage h into SMEM (512 threads x 1 float), then read via LDS
        sh[tid] = hp[tid];
        __syncthreads();

        float hv[16];
#pragma unroll
        for (int q = 0; q < 4; q++) {
            float4 v = *(const float4*)&sh[lane * 16 + q * 4];
            hv[q * 4 + 0] = v.x; hv[q * 4 + 1] = v.y;
            hv[q * 4 + 2] = v.z; hv[q * 4 + 3] = v.w;
        }

        float a0 = 0.f, a1 = 0.f, a2 = 0.f, a3 = 0.f;
#pragma unroll
        for (int k = 0; k < 16; k++) {
            a0 = fmaf(hv[k], wr[0][k], a0);
            a1 = fmaf(hv[k], wr[1][k], a1);
            a2 = fmaf(hv[k], wr[2][k], a2);
            a3 = fmaf(hv[k], wr[3][k], a3);
        }
#pragma unroll
        for (int off = 16; off > 0; off >>= 1) {
            a0 += __shfl_xor_sync(0xFFFFFFFFu, a0, off);
            a1 += __shfl_xor_sync(0xFFFFFFFFu, a1, off);
            a2 += __shfl_xor_sync(0xFFFFFFFFu, a2, off);
            a3 += __shfl_xor_sync(0xFFFFFFFFu, a3, off);
        }

        // gates distributed: lane k (k<4) computes activation of gate k
        const float pre = ((lane == 0) ? a0 : (lane == 1) ? a1
                          : (lane == 2) ? a2 : a3) + xv;
        const float sg = sigmoid_f(pre);
        const float th = tanh_f(pre);
        const float act = (lane == 2) ? th : sg;

        const float ig = __shfl_sync(0xFFFFFFFFu, act, 0);
        const float fg = __shfl_sync(0xFFFFFFFFu, act, 1);
        const float tg = __shfl_sync(0xFFFFFFFFu, act, 2);
        const float og = __shfl_sync(0xFFFFFFFFu, act, 3);

        c = fg * c + ig * tg;                 // replicated on all lanes
        const float hvout = og * tanh_f(c);
        if (lane == 0) g_hs[dir][t][hidx] = hvout;

        __syncthreads();                      // order h stores + protect sh reuse
        if (tid == 0) {
            asm volatile("st.release.gpu.global.b32 [%0], %1;"
                         :: "l"(myflag), "r"(s + 1) : "memory");
        }
    }
}

// ---------------- feats: [S, NT] = [hf|hb] @ w_out^T + b_out ---------------
__global__ void feats_kernel(const float* __restrict__ w_out,
                             const float* __restrict__ b_out)
{
    const int t = blockIdx.x;
    const int tid = threadIdx.x;   // 128
    float par[NT];
#pragma unroll
    for (int g = 0; g < NT; g++) par[g] = 0.f;

    for (int j = tid; j < HD; j += 128) {
        const float hf = g_hs[0][t][j];
        const float hb = g_hs[1][t][j];
#pragma unroll
        for (int g = 0; g < NT; g++)
            par[g] += hf * w_out[g * 1024 + j] + hb * w_out[g * 1024 + HD + j];
    }
#pragma unroll
    for (int off = 16; off > 0; off >>= 1)
#pragma unroll
        for (int g = 0; g < NT; g++)
            par[g] += __shfl_xor_sync(0xFFFFFFFFu, par[g], off);

    __shared__ float sm[NT][4];
    if ((tid & 31) == 0)
#pragma unroll
        for (int g = 0; g < NT; g++) sm[g][tid >> 5] = par[g];
    __syncthreads();
    if (tid < NT)
        g_feats[t][tid] = sm[tid][0] + sm[tid][1] + sm[tid][2] + sm[tid][3] + b_out[tid];
}

// ---------------- CRF: forward scan + gold score ---------------------------
// warp0: lane i owns tag i. Factorized: E_ij = exp(tr_ij) precomputed once;
// per step only exp(prev) (1 MUFU) + gather + log. Rebase each step by live
// lane 2's value (single shuffle); offset accumulated in double.
// warp1: gold path score (double accumulation)
__global__ void crf_kernel(const float* __restrict__ trans,
                           const int* __restrict__ gold_tags,
                           float* __restrict__ out)
{
    const int tid = threadIdx.x;    // 64 threads
    __shared__ double s_gold;
    __shared__ double s_alpha;

    if (tid >= 32) {
        // gold score
        const int lane = tid - 32;
        double acc = 0.0;
        for (int t = lane; t < S; t += 32) {
            const int tc = gold_tags[t];
            const int tp = (t == 0) ? 0 /*START*/ : gold_tags[t - 1];
            acc += (double)trans[tc * NT + tp] + (double)g_feats[t][tc];
        }
#pragma unroll
        for (int off = 16; off > 0; off >>= 1)
            acc += __shfl_xor_sync(0xFFFFFFFFu, acc, off);
        if (lane == 0)
            s_gold = acc + (double)trans[1 * NT + gold_tags[S - 1]];  // END=1
    } else {
        const int i = tid;
        const bool act = (i < NT);
        float Erow[NT];
#pragma unroll
        for (int j = 0; j < NT; j++)
            Erow[j] = act ? __expf(trans[i * NT + j]) : 0.0f;

        // init alphas: START(lane0)=0, other live tags -1e6, inactive -inf-ish
        float prev = act ? ((i == 0) ? 0.f : -1e6f) : -3.0e38f;
        double base = 0.0;
        float fnext = act ? g_feats[0][i] : 0.f;

        for (int t = 0; t < S; t++) {
            const float feat = fnext;
            if (t + 1 < S) fnext = act ? g_feats[t + 1][i] : 0.f;

            const float e = __expf(prev);        // small after rebase
            float s0 = 0.f, s1 = 0.f, s2 = 0.f;
#pragma unroll
            for (int j = 0; j < 4; j++) {
                s0 = fmaf(__shfl_sync(0xFFFFFFFFu, e, j),     Erow[j],     s0);
                s1 = fmaf(__shfl_sync(0xFFFFFFFFu, e, j + 4), Erow[j + 4], s1);
                s2 = fmaf(__shfl_sync(0xFFFFFFFFu, e, j + 8), Erow[j + 8], s2);
            }
            const float pn = feat + __logf(s0 + s1 + s2);   // -inf ok
            const float d = __shfl_sync(0xFFFFFFFFu, pn, 2); // live tag ref
            base += (double)d;
            prev = act ? (pn - d) : -3.0e38f;
        }
        // alpha = base + logsumexp_i(prev_i + trans[END=1][i])
        float fv = act ? (prev + trans[1 * NT + i]) : -3.0e38f;
        float m = fv;
#pragma unroll
        for (int off = 16; off > 0; off >>= 1)
            m = fmaxf(m, __shfl_xor_sync(0xFFFFFFFFu, m, off));
        float e = act ? __expf(fv - m) : 0.f;
#pragma unroll
        for (int off = 16; off > 0; off >>= 1)
            e += __shfl_xor_sync(0xFFFFFFFFu, e, off);
        if (tid == 0)
            s_alpha = base + (double)m + log((double)e);
    }
    __syncthreads();
    if (tid == 0)
        out[0] = (float)(s_alpha - s_gold);
}

// ---------------------------------------------------------------------------
extern "C" void kernel_launch(void* const* d_in, const int* in_sizes, int n_in,
                              void* d_out, int out_size)
{
    const int*   sentence = (const int*)  d_in[0];
    const int*   gold     = (const int*)  d_in[1];
    const float* emb      = (const float*)d_in[2];
    const float* wih_f    = (const float*)d_in[3];
    const float* whh_f    = (const float*)d_in[4];
    const float* b_f      = (const float*)d_in[5];
    const float* wih_b    = (const float*)d_in[6];
    const float* whh_b    = (const float*)d_in[7];
    const float* b_b      = (const float*)d_in[8];
    const float* w_out    = (const float*)d_in[9];
    const float* b_out    = (const float*)d_in[10];
    const float* trans    = (const float*)d_in[11];
    const float* h0       = (const float*)d_in[12];
    const float* c0       = (const float*)d_in[13];
    float* out = (float*)d_out;

    zero_flags_kernel<<<1, 64>>>();

    dim3 gg(G4 / 128, S / 128, 2);
    xproj_kernel<<<gg, 256>>>(sentence, emb, wih_f, b_f, wih_b, b_b);

    lstm_kernel<<<64, 512>>>(whh_f, whh_b, h0, c0);

    feats_kernel<<<S, 128>>>(w_out, b_out);

    crf_kernel<<<1, 64>>>(trans, gold, out);
}

// round 10
// speedup vs baseline: 3.4620x; 1.2041x over previous
#include <cuda_runtime.h>
#include <math.h>

#define S 2048
#define E 512
#define HD 512
#define G4 2048   /* 4*HD */
#define NT 12     /* tags */

typedef unsigned long long ull;

// ---------------- scratch (device globals; no runtime allocation) ----------
__device__ float g_xp[2][S][G4];     // input projections + bias, both dirs (32 MB)
__device__ float g_hs[2][S][HD];     // hidden states (for feats), both dirs
__device__ float g_feats[S][NT];     // emission features
__device__ ull   g_hp[2][2][HD];     // tagged h pairs: [dir][step&1][h] = (tag<<32)|bits

// ---------------------------------------------------------------------------
__global__ void zero_pairs_kernel() {   // clear stale tags from prior replays
    int i = blockIdx.x * blockDim.x + threadIdx.x;
    if (i < 2 * 2 * HD) ((ull*)g_hp)[i] = 0ull;
}

// ---------------- xproj GEMM: C[t][row] = x[t] . Wih[row] + b[row] ---------
// BM=BN=128, BK=16, 256 threads, 8x8 microtile
__global__ void __launch_bounds__(256) xproj_kernel(
    const int* __restrict__ sentence, const float* __restrict__ emb,
    const float* __restrict__ wih_f, const float* __restrict__ b_f,
    const float* __restrict__ wih_b, const float* __restrict__ b_b)
{
    __shared__ float As[16][128];
    __shared__ float Bs[16][128];

    const int dir = blockIdx.z;
    const float* __restrict__ wih  = dir ? wih_b : wih_f;
    const float* __restrict__ bias = dir ? b_b  : b_f;
    const int m0 = blockIdx.y * 128;   // t tile
    const int n0 = blockIdx.x * 128;   // gate-row tile
    const int tid = threadIdx.x;

    const int lr = tid >> 1;           // 0..127
    const int lk = (tid & 1) * 8;      // 0 or 8
    const float* arow = emb + (size_t)sentence[m0 + lr] * E + lk;
    const float* brow = wih + (size_t)(n0 + lr) * E + lk;

    const int tx = tid & 15, ty = tid >> 4;
    float acc[8][8];
#pragma unroll
    for (int i = 0; i < 8; i++)
#pragma unroll
        for (int j = 0; j < 8; j++) acc[i][j] = 0.f;

    for (int k0 = 0; k0 < E; k0 += 16) {
        float4 a0 = *(const float4*)(arow + k0);
        float4 a1 = *(const float4*)(arow + k0 + 4);
        float4 b0 = *(const float4*)(brow + k0);
        float4 b1 = *(const float4*)(brow + k0 + 4);
        __syncthreads();
        As[lk + 0][lr] = a0.x; As[lk + 1][lr] = a0.y; As[lk + 2][lr] = a0.z; As[lk + 3][lr] = a0.w;
        As[lk + 4][lr] = a1.x; As[lk + 5][lr] = a1.y; As[lk + 6][lr] = a1.z; As[lk + 7][lr] = a1.w;
        Bs[lk + 0][lr] = b0.x; Bs[lk + 1][lr] = b0.y; Bs[lk + 2][lr] = b0.z; Bs[lk + 3][lr] = b0.w;
        Bs[lk + 4][lr] = b1.x; Bs[lk + 5][lr] = b1.y; Bs[lk + 6][lr] = b1.z; Bs[lk + 7][lr] = b1.w;
        __syncthreads();
#pragma unroll
        for (int kk = 0; kk < 16; kk++) {
            float a[8], b[8];
            *(float4*)&a[0] = *(const float4*)&As[kk][ty * 8];
            *(float4*)&a[4] = *(const float4*)&As[kk][ty * 8 + 4];
            *(float4*)&b[0] = *(const float4*)&Bs[kk][tx * 8];
            *(float4*)&b[4] = *(const float4*)&Bs[kk][tx * 8 + 4];
#pragma unroll
            for (int i = 0; i < 8; i++)
#pragma unroll
                for (int j = 0; j < 8; j++)
                    acc[i][j] = fmaf(a[i], b[j], acc[i][j]);
        }
    }

    float bv[8];
#pragma unroll
    for (int j = 0; j < 8; j++) bv[j] = bias[n0 + tx * 8 + j];
#pragma unroll
    for (int i = 0; i < 8; i++) {
        const int m = m0 + ty * 8 + i;
        float4 o0, o1;
        o0.x = acc[i][0] + bv[0]; o0.y = acc[i][1] + bv[1];
        o0.z = acc[i][2] + bv[2]; o0.w = acc[i][3] + bv[3];
        o1.x = acc[i][4] + bv[4]; o1.y = acc[i][5] + bv[5];
        o1.z = acc[i][6] + bv[6]; o1.w = acc[i][7] + bv[7];
        *(float4*)&g_xp[dir][m][n0 + tx * 8]     = o0;
        *(float4*)&g_xp[dir][m][n0 + tx * 8 + 4] = o1;
    }
}

// ---------------- persistent bidirectional LSTM ----------------------------
// grid = 128 CTAs (64/dir), 256 threads (8 warps). warp w owns h-index
// cid*8+w. Lane holds k-slice {lane, lane+32, ..., lane+480} of each gate
// row (conflict-free stride-32 LDS reads). h exchanged as seqlock-style
// tagged 8B pairs (tag = step+1 in hi32, value bits in lo32) stored with
// st.relaxed.gpu.b64 -- no fences, no flags: the poll IS the data load.
// Double-buffered by step parity.
__device__ __forceinline__ float sigmoid_f(float x) {
    return __fdividef(1.0f, 1.0f + __expf(-x));
}
__device__ __forceinline__ float tanh_f(float x) {
    return 1.0f - 2.0f * __fdividef(1.0f, 1.0f + __expf(2.0f * x));
}
__device__ __forceinline__ ull ld_relaxed_u64(const ull* p) {
    ull v;
    asm volatile("ld.relaxed.gpu.global.b64 %0, [%1];" : "=l"(v) : "l"(p) : "memory");
    return v;
}
__device__ __forceinline__ void st_relaxed_u64(ull* p, ull v) {
    asm volatile("st.relaxed.gpu.global.b64 [%0], %1;" :: "l"(p), "l"(v) : "memory");
}

__global__ void __launch_bounds__(256, 1) lstm_kernel(
    const float* __restrict__ whh_f, const float* __restrict__ whh_b,
    const float* __restrict__ h0, const float* __restrict__ c0)
{
    const int dir  = blockIdx.x & 1;
    const int cid  = blockIdx.x >> 1;          // 0..63
    const int warp = threadIdx.x >> 5;         // 0..7
    const int lane = threadIdx.x & 31;
    const int tid  = threadIdx.x;
    const int hidx = cid * 8 + warp;           // 0..511

    __shared__ float sh[HD];                   // staged h (2KB)

    const float* __restrict__ whh = dir ? whh_b : whh_f;

    // lane's k-slice: k = lane + 32*j  (conflict-free SMEM reads later)
    float wr[4][16];
#pragma unroll
    for (int gg = 0; gg < 4; gg++) {
        const float* r = whh + (size_t)(gg * HD + hidx) * HD + lane;
#pragma unroll
        for (int j = 0; j < 16; j++)
            wr[gg][j] = r[32 * j];
    }
    float c = c0[dir * HD + hidx];   // replicated on all lanes

    int t = dir ? (S - 1) : 0;
    const int dt = dir ? -1 : 1;

    for (int s = 0; s < S; s++, t += dt) {
        // prefetch this lane's gate pre-activation (lane k<4 -> gate k)
        float xv = 0.0f;
        if (lane < 4) xv = g_xp[dir][t][lane * HD + hidx];

        // ---- acquire h(s-1) into sh ----
        if (s == 0) {
            float2 v = ((const float2*)(h0 + dir * HD))[tid];
            sh[2 * tid]     = v.x;
            sh[2 * tid + 1] = v.y;
        } else {
            const ull* bp = &g_hp[dir][(s - 1) & 1][0];
            const unsigned tagw = (unsigned)s;
            ull p0 = ld_relaxed_u64(bp + tid);
            ull p1 = ld_relaxed_u64(bp + tid + 256);
            int m0 = ((unsigned)(p0 >> 32) != tagw);
            int m1 = ((unsigned)(p1 >> 32) != tagw);
            while (__any_sync(0xFFFFFFFFu, m0 | m1)) {
                if (m0) { p0 = ld_relaxed_u64(bp + tid);
                          m0 = ((unsigned)(p0 >> 32) != tagw); }
                if (m1) { p1 = ld_relaxed_u64(bp + tid + 256);
                          m1 = ((unsigned)(p1 >> 32) != tagw); }
            }
            sh[tid]       = __uint_as_float((unsigned)p0);
            sh[tid + 256] = __uint_as_float((unsigned)p1);
        }
        __syncthreads();

        // ---- gate matvec: lane sums its stride-32 k-slice ----
        float a0 = 0.f, a1 = 0.f, a2 = 0.f, a3 = 0.f;
#pragma unroll
        for (int j = 0; j < 16; j++) {
            const float hv = sh[lane + 32 * j];     // conflict-free
            a0 = fmaf(hv, wr[0][j], a0);
            a1 = fmaf(hv, wr[1][j], a1);
            a2 = fmaf(hv, wr[2][j], a2);
            a3 = fmaf(hv, wr[3][j], a3);
        }
#pragma unroll
        for (int off = 16; off > 0; off >>= 1) {
            a0 += __shfl_xor_sync(0xFFFFFFFFu, a0, off);
            a1 += __shfl_xor_sync(0xFFFFFFFFu, a1, off);
            a2 += __shfl_xor_sync(0xFFFFFFFFu, a2, off);
            a3 += __shfl_xor_sync(0xFFFFFFFFu, a3, off);
        }

        // gates distributed: lane k (k<4) computes activation of gate k
        const float pre = ((lane == 0) ? a0 : (lane == 1) ? a1
                          : (lane == 2) ? a2 : a3) + xv;
        const float sg = sigmoid_f(pre);
        const float th = tanh_f(pre);
        const float act = (lane == 2) ? th : sg;

        const float ig = __shfl_sync(0xFFFFFFFFu, act, 0);
        const float fg = __shfl_sync(0xFFFFFFFFu, act, 1);
        const float tg = __shfl_sync(0xFFFFFFFFu, act, 2);
        const float og = __shfl_sync(0xFFFFFFFFu, act, 3);

        c = fg * c + ig * tg;                 // replicated on all lanes
        const float hvout = og * tanh_f(c);
        if (lane == 0) {
            const ull pair = ((ull)(unsigned)(s + 1) << 32)
                           | (ull)(unsigned)__float_as_uint(hvout);
            st_relaxed_u64(&g_hp[dir][s & 1][hidx], pair);   // publish (atomic 8B)
            g_hs[dir][t][hidx] = hvout;                      // for feats
        }
        __syncthreads();                      // protect sh reuse next step
    }
}

// ---------------- feats: [S, NT] = [hf|hb] @ w_out^T + b_out ---------------
__global__ void feats_kernel(const float* __restrict__ w_out,
                             const float* __restrict__ b_out)
{
    const int t = blockIdx.x;
    const int tid = threadIdx.x;   // 128
    float par[NT];
#pragma unroll
    for (int g = 0; g < NT; g++) par[g] = 0.f;

    for (int j = tid; j < HD; j += 128) {
        const float hf = g_hs[0][t][j];
        const float hb = g_hs[1][t][j];
#pragma unroll
        for (int g = 0; g < NT; g++)
            par[g] += hf * w_out[g * 1024 + j] + hb * w_out[g * 1024 + HD + j];
    }
#pragma unroll
    for (int off = 16; off > 0; off >>= 1)
#pragma unroll
        for (int g = 0; g < NT; g++)
            par[g] += __shfl_xor_sync(0xFFFFFFFFu, par[g], off);

    __shared__ float sm[NT][4];
    if ((tid & 31) == 0)
#pragma unroll
        for (int g = 0; g < NT; g++) sm[g][tid >> 5] = par[g];
    __syncthreads();
    if (tid < NT)
        g_feats[t][tid] = sm[tid][0] + sm[tid][1] + sm[tid][2] + sm[tid][3] + b_out[tid];
}

// ---------------- CRF: forward scan + gold score ---------------------------
// warp0: lane i owns tag i. Factorized: E_ij = exp(tr_ij) precomputed once;
// per step only exp(prev) (1 MUFU) + gather + log. Rebase each step by live
// lane 2's value (single shuffle); offset accumulated in double.
// warp1: gold path score (double accumulation)
__global__ void crf_kernel(const float* __restrict__ trans,
                           const int* __restrict__ gold_tags,
                           float* __restrict__ out)
{
    const int tid = threadIdx.x;    // 64 threads
    __shared__ double s_gold;
    __shared__ double s_alpha;

    if (tid >= 32) {
        // gold score
        const int lane = tid - 32;
        double acc = 0.0;
        for (int t = lane; t < S; t += 32) {
            const int tc = gold_tags[t];
            const int tp = (t == 0) ? 0 /*START*/ : gold_tags[t - 1];
            acc += (double)trans[tc * NT + tp] + (double)g_feats[t][tc];
        }
#pragma unroll
        for (int off = 16; off > 0; off >>= 1)
            acc += __shfl_xor_sync(0xFFFFFFFFu, acc, off);
        if (lane == 0)
            s_gold = acc + (double)trans[1 * NT + gold_tags[S - 1]];  // END=1
    } else {
        const int i = tid;
        const bool act = (i < NT);
        float Erow[NT];
#pragma unroll
        for (int j = 0; j < NT; j++)
            Erow[j] = act ? __expf(trans[i * NT + j]) : 0.0f;

        // init alphas: START(lane0)=0, other live tags -1e6, inactive -inf-ish
        float prev = act ? ((i == 0) ? 0.f : -1e6f) : -3.0e38f;
        double base = 0.0;
        float fnext = act ? g_feats[0][i] : 0.f;

        for (int t = 0; t < S; t++) {
            const float feat = fnext;
            if (t + 1 < S) fnext = act ? g_feats[t + 1][i] : 0.f;

            const float e = __expf(prev);        // small after rebase
            float s0 = 0.f, s1 = 0.f, s2 = 0.f;
#pragma unroll
            for (int j = 0; j < 4; j++) {
                s0 = fmaf(__shfl_sync(0xFFFFFFFFu, e, j),     Erow[j],     s0);
                s1 = fmaf(__shfl_sync(0xFFFFFFFFu, e, j + 4), Erow[j + 4], s1);
                s2 = fmaf(__shfl_sync(0xFFFFFFFFu, e, j + 8), Erow[j + 8], s2);
            }
            const float pn = feat + __logf(s0 + s1 + s2);   // -inf ok
            const float d = __shfl_sync(0xFFFFFFFFu, pn, 2); // live tag ref
            base += (double)d;
            prev = act ? (pn - d) : -3.0e38f;
        }
        // alpha = base + logsumexp_i(prev_i + trans[END=1][i])
        float fv = act ? (prev + trans[1 * NT + i]) : -3.0e38f;
        float m = fv;
#pragma unroll
        for (int off = 16; off > 0; off >>= 1)
            m = fmaxf(m, __shfl_xor_sync(0xFFFFFFFFu, m, off));
        float e = act ? __expf(fv - m) : 0.f;
#pragma unroll
        for (int off = 16; off > 0; off >>= 1)
            e += __shfl_xor_sync(0xFFFFFFFFu, e, off);
        if (tid == 0)
            s_alpha = base + (double)m + log((double)e);
    }
    __syncthreads();
    if (tid == 0)
        out[0] = (float)(s_alpha - s_gold);
}

// ---------------------------------------------------------------------------
extern "C" void kernel_launch(void* const* d_in, const int* in_sizes, int n_in,
                              void* d_out, int out_size)
{
    const int*   sentence = (const int*)  d_in[0];
    const int*   gold     = (const int*)  d_in[1];
    const float* emb      = (const float*)d_in[2];
    const float* wih_f    = (const float*)d_in[3];
    const float* whh_f    = (const float*)d_in[4];
    const float* b_f      = (const float*)d_in[5];
    const float* wih_b    = (const float*)d_in[6];
    const float* whh_b    = (const float*)d_in[7];
    const float* b_b      = (const float*)d_in[8];
    const float* w_out    = (const float*)d_in[9];
    const float* b_out    = (const float*)d_in[10];
    const float* trans    = (const float*)d_in[11];
    const float* h0       = (const float*)d_in[12];
    const float* c0       = (const float*)d_in[13];
    float* out = (float*)d_out;

    zero_pairs_kernel<<<8, 256>>>();

    dim3 gg(G4 / 128, S / 128, 2);
    xproj_kernel<<<gg, 256>>>(sentence, emb, wih_f, b_f, wih_b, b_b);

    lstm_kernel<<<128, 256>>>(whh_f, whh_b, h0, c0);

    feats_kernel<<<S, 128>>>(w_out, b_out);

    crf_kernel<<<1, 64>>>(trans, gold, out);
}